// round 5
// baseline (speedup 1.0000x reference)
#include <cuda_runtime.h>
#include <cuda_bf16.h>
#include <cstdint>

// ---------------------------------------------------------------------------
// HungarianMatcher cost matrix. B=16 Q=900 C=91 T=4800, out [14400,4800] f32.
//
// R5 (from R4: alu pipe 52.7% is the top consumer = FMNMX + MOV + IADD):
//  - enclosing box via min+max=sum identity: enc_w = (wr + wt) - sw
//    -> 4 corner FMNMX deleted (alu), replaced by FADDs (fma has headroom)
//  - per-box extras packed {w, h, area, cls} -> one LDG.128 each side
//  - __stcs with immediate offsets (no per-store 64-bit address adds)
//  - unchanged: negated corners, f32x2 packed L1 diffs, single-rcp giou,
//    16 rows x 192 targets tile, zero tail predicates
// ---------------------------------------------------------------------------

#define BQ_MAX   14400
#define T_MAX    4800
#define NCLS     91
#define CP       92

__device__ float  g_F[BQ_MAX * CP];     // 2*(pos-neg) focal, row-major
__device__ float4 g_tgtA[T_MAX];        // -5*cxcywh  (negated)
__device__ float4 g_tgtB[T_MAX];        // {-x0,-y0, x1, y1}
__device__ float4 g_tgtE[T_MAX];        // {w, h, area, asfloat(cls*4)}
__device__ float4 g_rowA[BQ_MAX];       // +5*cxcywh
__device__ float4 g_rowB[BQ_MAX];       // {-x0,-y0, x1, y1}
__device__ float4 g_rowE[BQ_MAX];       // {w, h, area, 0}

__device__ __forceinline__ float frcp_approx(float x) {
    float r;
    asm("rcp.approx.f32 %0, %1;" : "=f"(r) : "f"(x));
    return r;
}

#define ADD_F32X2(out, a, b) \
    asm("add.rn.f32x2 %0, %1, %2;" : "=l"(out) : "l"(a), "l"(b))
#define UNPACK2F(lo, hi, in) \
    asm("mov.b64 {%0, %1}, %2;" : "=f"(lo), "=f"(hi) : "l"(in))

// ---------------------------- prep: focal table ----------------------------
__global__ void prep_focal(const float* __restrict__ logits, int BQ, int C) {
    int i = blockIdx.x * blockDim.x + threadIdx.x;
    if (i >= BQ * C) return;
    int row = i / C;
    int c   = i - row * C;
    float x = logits[i];
    float e = __expf(-x);
    float inv = frcp_approx(1.0f + e);
    float p = inv;          // sigmoid
    float q = e * inv;      // 1 - sigmoid, no cancellation
    float lp = __logf(p + 1e-8f);
    float lq = __logf(q + 1e-8f);
    g_F[row * CP + c] = -0.5f * q * q * lp + 1.5f * p * p * lq; // 2*(pos-neg)
}

// ---------------------------- prep: row boxes -------------------------------
__global__ void prep_rows(const float* __restrict__ boxes, int BQ) {
    int r = blockIdx.x * blockDim.x + threadIdx.x;
    if (r >= BQ) return;
    float4 b = reinterpret_cast<const float4*>(boxes)[r];  // cx,cy,w,h
    g_rowA[r] = make_float4(5.f*b.x, 5.f*b.y, 5.f*b.z, 5.f*b.w);
    float x0 = b.x - 0.5f*b.z, y0 = b.y - 0.5f*b.w;
    float x1 = b.x + 0.5f*b.z, y1 = b.y + 0.5f*b.w;
    float w = x1 - x0, h = y1 - y0;
    g_rowB[r] = make_float4(-x0, -y0, x1, y1);
    g_rowE[r] = make_float4(w, h, w * h, 0.f);
}

// ---------------------------- prep: tgt boxes -------------------------------
__global__ void prep_tgts(const float* __restrict__ boxes,
                          const int* __restrict__ ids, int T) {
    int t = blockIdx.x * blockDim.x + threadIdx.x;
    if (t >= T) return;
    float4 b = reinterpret_cast<const float4*>(boxes)[t];
    g_tgtA[t] = make_float4(-5.f*b.x, -5.f*b.y, -5.f*b.z, -5.f*b.w);
    float x0 = b.x - 0.5f*b.z, y0 = b.y - 0.5f*b.w;
    float x1 = b.x + 0.5f*b.z, y1 = b.y + 0.5f*b.w;
    float w = x1 - x0, h = y1 - y0;
    g_tgtB[t] = make_float4(-x0, -y0, x1, y1);
    g_tgtE[t] = make_float4(w, h, w * h, __int_as_float((ids[t] - 1) * 4));
}

// ---------------------------- main kernel -----------------------------------
// Block 256 threads = 16 rows x 192 targets (4800 = 25*192, 14400 = 900*16).
//   rr = tid>>6 -> rows row0 + rr*4 + r, r in 0..3 (warp-uniform)
//   tt = tid&63 -> targets base + tt + k*64, k in 0..2 (coalesced)
#define ROW_TILE 16
#define TGT_TILE 192

__global__ void __launch_bounds__(256, 4)
cost_kernel(float* __restrict__ out, int T) {
    const int tid  = threadIdx.x;
    const int tt   = tid & 63;
    const int rr   = tid >> 6;
    const int row0 = blockIdx.y * ROW_TILE + (rr << 2);
    const int base = blockIdx.x * TGT_TILE + tt;

    // ---- 3 targets in registers (all loads coalesced) ----
    unsigned long long taL[3], taH[3];   // packed (-5cx,-5cy) / (-5w,-5h)
    float4 tb[3], tE[3];
    const float* q[3];                   // gather base: &g_F[row0*CP + cls_k]
    {
        const char* fbase = reinterpret_cast<const char*>(g_F)
                          + (size_t)row0 * (CP * 4);
        #pragma unroll
        for (int k = 0; k < 3; ++k) {
            const int j = base + (k << 6);
            ulonglong2 a = *reinterpret_cast<const ulonglong2*>(&g_tgtA[j]);
            taL[k] = a.x;  taH[k] = a.y;
            tb[k]  = g_tgtB[j];
            tE[k]  = g_tgtE[j];
            q[k] = reinterpret_cast<const float*>(fbase
                        + __float_as_int(tE[k].w));
        }
    }

    #pragma unroll
    for (int r = 0; r < 4; ++r) {
        const int row = row0 + r;
        const ulonglong2 rA2 = *reinterpret_cast<const ulonglong2*>(&g_rowA[row]);
        const float4 rB = g_rowB[row];
        const float4 rE = g_rowE[row];      // {wr, hr, area, -}
        float* dst = out + (size_t)row * T + base;

        #pragma unroll
        for (int k = 0; k < 3; ++k) {
            // focal gather: warp-uniform row, lanes span 368B (~3 L1 lines)
            const float f2 = __ldg(q[k] + r * CP);

            // ---- 5*L1: packed diffs (rA=+5c, ta=-5c), abs folds into FADD
            unsigned long long dxy, dzw;
            ADD_F32X2(dxy, rA2.x, taL[k]);
            ADD_F32X2(dzw, rA2.y, taH[k]);
            float d0, d1, d2, d3;
            UNPACK2F(d0, d1, dxy);
            UNPACK2F(d2, d3, dzw);
            float bx = (fabsf(d0) + fabsf(d1)) + (fabsf(d2) + fabsf(d3));

            // ---- intersection corners (only 4 FMNMX; negated data) ----
            float mltx = fminf(rB.x, tb[k].x);   // = -max(x0a,x0b)
            float mlty = fminf(rB.y, tb[k].y);
            float rbx  = fminf(rB.z, tb[k].z);   // =  min(x1a,x1b)
            float rby  = fminf(rB.w, tb[k].w);
            float sw = rbx + mltx;               // signed inter width
            float sh = rby + mlty;
            float iw = fmaxf(sw, 0.0f);
            float ih = fmaxf(sh, 0.0f);
            float inter = iw * ih;

            // ---- enclosing box via min+max=sum identity (no FMNMX) ----
            float encw = (rE.x + tE[k].x) - sw;  // max(x1)-min(x0)
            float ench = (rE.y + tE[k].y) - sh;
            float enc  = encw * ench;

            float uni = (rE.z + tE[k].z) - inter;
            float dd  = enc - uni;
            float u = fmaxf(uni, 1e-6f);
            float e = fmaxf(enc, 1e-6f);
            float num = fmaf(dd, -u, inter * e); // giou = num/(u*e)
            float inv = frcp_approx(u * e);

            float res = fmaf(num * inv, -2.0f, f2 + bx);
            __stcs(dst + (k << 6), res);         // STG.CS [R+imm], coalesced
        }
    }
}

// ---------------------------------------------------------------------------
extern "C" void kernel_launch(void* const* d_in, const int* in_sizes, int n_in,
                              void* d_out, int out_size) {
    const float* pred_logits = (const float*)d_in[0];
    const float* pred_boxes  = (const float*)d_in[1];
    const int*   tgt_ids     = (const int*)d_in[2];
    const float* tgt_boxes   = (const float*)d_in[3];
    float* out = (float*)d_out;

    const int BQ = in_sizes[1] / 4;          // 14400
    const int C  = in_sizes[0] / BQ;         // 91
    const int T  = in_sizes[2];              // 4800

    prep_focal<<<(BQ * C + 255) / 256, 256>>>(pred_logits, BQ, C);
    prep_rows <<<(BQ + 255) / 256, 256>>>(pred_boxes, BQ);
    prep_tgts <<<(T + 255) / 256, 256>>>(tgt_boxes, tgt_ids, T);

    // T=4800 and BQ=14400 divide exactly: no tail handling needed
    dim3 grid(T / TGT_TILE, BQ / ROW_TILE);
    cost_kernel<<<grid, 256>>>(out, T);
}

// round 6
// speedup vs baseline: 1.0694x; 1.0694x over previous
#include <cuda_runtime.h>
#include <cuda_bf16.h>
#include <cstdint>

// ---------------------------------------------------------------------------
// HungarianMatcher cost matrix. B=16 Q=900 C=91 T=4800, out [14400,4800] f32.
//
// R6 (from R5: stall/latency-bound, L1tex 62% top, issue 61%):
//  - 8 rows per thread (ROW_TILE=32): 9 target LDG.128s amortized over 24
//    elems (was 12) -> target-load wavefronts/elem halved; 24 independent
//    elements per thread restores ILP for latency hiding
//  - focal stride padded 92->96 floats: rows 128B-aligned, warp gathers span
//    exactly <=3 cache lines
//  - unchanged: negated corners, min+max=sum enclosing identity, f32x2 L1
//    diffs, single-rcp giou, streaming stores, zero tail predicates
// ---------------------------------------------------------------------------

#define BQ_MAX   14400
#define T_MAX    4800
#define NCLS     91
#define CP       96            // padded class stride (row = 384B, 128B-aligned)

__device__ __align__(128) float g_F[BQ_MAX * CP];  // 2*(pos-neg) focal
__device__ float4 g_tgtA[T_MAX];        // -5*cxcywh  (negated)
__device__ float4 g_tgtB[T_MAX];        // {-x0,-y0, x1, y1}
__device__ float4 g_tgtE[T_MAX];        // {w, h, area, asfloat(cls*4)}
__device__ float4 g_rowA[BQ_MAX];       // +5*cxcywh
__device__ float4 g_rowB[BQ_MAX];       // {-x0,-y0, x1, y1}
__device__ float4 g_rowE[BQ_MAX];       // {w, h, area, 0}

__device__ __forceinline__ float frcp_approx(float x) {
    float r;
    asm("rcp.approx.f32 %0, %1;" : "=f"(r) : "f"(x));
    return r;
}

#define ADD_F32X2(out, a, b) \
    asm("add.rn.f32x2 %0, %1, %2;" : "=l"(out) : "l"(a), "l"(b))
#define UNPACK2F(lo, hi, in) \
    asm("mov.b64 {%0, %1}, %2;" : "=f"(lo), "=f"(hi) : "l"(in))

// ---------------------------- prep: focal table ----------------------------
__global__ void prep_focal(const float* __restrict__ logits, int BQ, int C) {
    int i = blockIdx.x * blockDim.x + threadIdx.x;
    if (i >= BQ * C) return;
    int row = i / C;
    int c   = i - row * C;
    float x = logits[i];
    float e = __expf(-x);
    float inv = frcp_approx(1.0f + e);
    float p = inv;          // sigmoid
    float q = e * inv;      // 1 - sigmoid, no cancellation
    float lp = __logf(p + 1e-8f);
    float lq = __logf(q + 1e-8f);
    g_F[row * CP + c] = -0.5f * q * q * lp + 1.5f * p * p * lq; // 2*(pos-neg)
}

// ---------------------------- prep: row boxes -------------------------------
__global__ void prep_rows(const float* __restrict__ boxes, int BQ) {
    int r = blockIdx.x * blockDim.x + threadIdx.x;
    if (r >= BQ) return;
    float4 b = reinterpret_cast<const float4*>(boxes)[r];  // cx,cy,w,h
    g_rowA[r] = make_float4(5.f*b.x, 5.f*b.y, 5.f*b.z, 5.f*b.w);
    float x0 = b.x - 0.5f*b.z, y0 = b.y - 0.5f*b.w;
    float x1 = b.x + 0.5f*b.z, y1 = b.y + 0.5f*b.w;
    float w = x1 - x0, h = y1 - y0;
    g_rowB[r] = make_float4(-x0, -y0, x1, y1);
    g_rowE[r] = make_float4(w, h, w * h, 0.f);
}

// ---------------------------- prep: tgt boxes -------------------------------
__global__ void prep_tgts(const float* __restrict__ boxes,
                          const int* __restrict__ ids, int T) {
    int t = blockIdx.x * blockDim.x + threadIdx.x;
    if (t >= T) return;
    float4 b = reinterpret_cast<const float4*>(boxes)[t];
    g_tgtA[t] = make_float4(-5.f*b.x, -5.f*b.y, -5.f*b.z, -5.f*b.w);
    float x0 = b.x - 0.5f*b.z, y0 = b.y - 0.5f*b.w;
    float x1 = b.x + 0.5f*b.z, y1 = b.y + 0.5f*b.w;
    float w = x1 - x0, h = y1 - y0;
    g_tgtB[t] = make_float4(-x0, -y0, x1, y1);
    g_tgtE[t] = make_float4(w, h, w * h, __int_as_float((ids[t] - 1) * 4));
}

// ---------------------------- main kernel -----------------------------------
// Block 256 threads = 32 rows x 192 targets (4800 = 25*192, 14400 = 450*32).
//   rr = tid>>6 -> rows row0 + rr*8 + r, r in 0..7 (warp-uniform)
//   tt = tid&63 -> targets base + tt + k*64, k in 0..2 (coalesced)
#define ROW_TILE 32
#define TGT_TILE 192
#define RPT      8              // rows per thread

__global__ void __launch_bounds__(256, 4)
cost_kernel(float* __restrict__ out, int T) {
    const int tid  = threadIdx.x;
    const int tt   = tid & 63;
    const int rr   = tid >> 6;
    const int row0 = blockIdx.y * ROW_TILE + rr * RPT;
    const int base = blockIdx.x * TGT_TILE + tt;

    // ---- 3 targets in registers (all loads coalesced across lanes) ----
    unsigned long long taL[3], taH[3];   // packed (-5cx,-5cy) / (-5w,-5h)
    float4 tb[3], tE[3];
    const float* q[3];                   // gather base: &g_F[row0*CP + cls_k]
    {
        const char* fbase = reinterpret_cast<const char*>(g_F)
                          + (size_t)row0 * (CP * 4);
        #pragma unroll
        for (int k = 0; k < 3; ++k) {
            const int j = base + (k << 6);
            ulonglong2 a = *reinterpret_cast<const ulonglong2*>(&g_tgtA[j]);
            taL[k] = a.x;  taH[k] = a.y;
            tb[k]  = g_tgtB[j];
            tE[k]  = g_tgtE[j];
            q[k] = reinterpret_cast<const float*>(fbase
                        + __float_as_int(tE[k].w));
        }
    }

    float* dst0 = out + (size_t)row0 * T + base;

    #pragma unroll
    for (int r = 0; r < RPT; ++r) {
        const int row = row0 + r;
        // warp-uniform row loads (broadcast, 1 wavefront each)
        const ulonglong2 rA2 = *reinterpret_cast<const ulonglong2*>(&g_rowA[row]);
        const float4 rB = g_rowB[row];
        const float4 rE = g_rowE[row];      // {wr, hr, area, -}
        float* dst = dst0 + (size_t)r * T;

        #pragma unroll
        for (int k = 0; k < 3; ++k) {
            // focal gather: row 128B-aligned, lanes span <=3 L1 lines
            const float f2 = __ldg(q[k] + r * CP);

            // ---- 5*L1: packed diffs (rA=+5c, ta=-5c), abs folds into FADD
            unsigned long long dxy, dzw;
            ADD_F32X2(dxy, rA2.x, taL[k]);
            ADD_F32X2(dzw, rA2.y, taH[k]);
            float d0, d1, d2, d3;
            UNPACK2F(d0, d1, dxy);
            UNPACK2F(d2, d3, dzw);
            float bx = (fabsf(d0) + fabsf(d1)) + (fabsf(d2) + fabsf(d3));

            // ---- intersection corners (4 FMNMX; negated data) ----
            float mltx = fminf(rB.x, tb[k].x);   // = -max(x0a,x0b)
            float mlty = fminf(rB.y, tb[k].y);
            float rbx  = fminf(rB.z, tb[k].z);   // =  min(x1a,x1b)
            float rby  = fminf(rB.w, tb[k].w);
            float sw = rbx + mltx;               // signed inter width
            float sh = rby + mlty;
            float iw = fmaxf(sw, 0.0f);
            float ih = fmaxf(sh, 0.0f);
            float inter = iw * ih;

            // ---- enclosing box via min+max=sum identity (no FMNMX) ----
            float encw = (rE.x + tE[k].x) - sw;  // max(x1)-min(x0)
            float ench = (rE.y + tE[k].y) - sh;
            float enc  = encw * ench;

            float uni = (rE.z + tE[k].z) - inter;
            float dd  = enc - uni;
            float u = fmaxf(uni, 1e-6f);
            float e = fmaxf(enc, 1e-6f);
            float num = fmaf(dd, -u, inter * e); // giou = num/(u*e)
            float inv = frcp_approx(u * e);

            float res = fmaf(num * inv, -2.0f, f2 + bx);
            __stcs(dst + (k << 6), res);         // STG.CS, coalesced
        }
    }
}

// ---------------------------------------------------------------------------
extern "C" void kernel_launch(void* const* d_in, const int* in_sizes, int n_in,
                              void* d_out, int out_size) {
    const float* pred_logits = (const float*)d_in[0];
    const float* pred_boxes  = (const float*)d_in[1];
    const int*   tgt_ids     = (const int*)d_in[2];
    const float* tgt_boxes   = (const float*)d_in[3];
    float* out = (float*)d_out;

    const int BQ = in_sizes[1] / 4;          // 14400
    const int C  = in_sizes[0] / BQ;         // 91
    const int T  = in_sizes[2];              // 4800

    prep_focal<<<(BQ * C + 255) / 256, 256>>>(pred_logits, BQ, C);
    prep_rows <<<(BQ + 255) / 256, 256>>>(pred_boxes, BQ);
    prep_tgts <<<(T + 255) / 256, 256>>>(tgt_boxes, tgt_ids, T);

    // exact tiling: 4800 = 25*192, 14400 = 450*32
    dim3 grid(T / TGT_TILE, BQ / ROW_TILE);
    cost_kernel<<<grid, 256>>>(out, T);
}

// round 7
// speedup vs baseline: 1.1519x; 1.0771x over previous
#include <cuda_runtime.h>
#include <cuda_bf16.h>
#include <cstdint>

// ---------------------------------------------------------------------------
// HungarianMatcher cost matrix. B=16 Q=900 C=91 T=4800, out [14400,4800] f32.
//
// R7 (from R6: latency-bound; focal gather = longest chain + largest L1 item):
//  - focal table interleaved by ROW QUAD: g_F[(row>>2)*4*CP + c*4 + (row&3)]
//    -> one LDG.128 gather yields f2 for 4 rows; 6 vector gathers per
//    warp-tile (was 24 scalar), each feeding 12 elements of register math
//  - per-quad streaming loop; launch_bounds(256,3) = 84 regs so gathered
//    values + 3 targets live in registers without spills
//  - unchanged: negated corners, min+max=sum enclosing identity, f32x2 L1
//    diffs, single-rcp giou, streaming stores, exact tiling (no predicates)
// ---------------------------------------------------------------------------

#define BQ_MAX   14400
#define T_MAX    4800
#define NCLS     91
#define CP       96            // class stride (quad block = 4*CP = 1536B)

__device__ __align__(128) float g_F[BQ_MAX * CP];  // quad-interleaved focal
__device__ float4 g_tgtA[T_MAX];        // -5*cxcywh  (negated)
__device__ float4 g_tgtB[T_MAX];        // {-x0,-y0, x1, y1}
__device__ float4 g_tgtE[T_MAX];        // {w, h, area, asfloat(cls*16)}
__device__ float4 g_rowA[BQ_MAX];       // +5*cxcywh
__device__ float4 g_rowB[BQ_MAX];       // {-x0,-y0, x1, y1}
__device__ float4 g_rowE[BQ_MAX];       // {w, h, area, 0}

__device__ __forceinline__ float frcp_approx(float x) {
    float r;
    asm("rcp.approx.f32 %0, %1;" : "=f"(r) : "f"(x));
    return r;
}

#define ADD_F32X2(out, a, b) \
    asm("add.rn.f32x2 %0, %1, %2;" : "=l"(out) : "l"(a), "l"(b))
#define UNPACK2F(lo, hi, in) \
    asm("mov.b64 {%0, %1}, %2;" : "=f"(lo), "=f"(hi) : "l"(in))

// ---------------------------- prep: focal table ----------------------------
// writes quad-interleaved: [(row>>2)][c][row&3]
__global__ void prep_focal(const float* __restrict__ logits, int BQ, int C) {
    int i = blockIdx.x * blockDim.x + threadIdx.x;
    if (i >= BQ * C) return;
    int row = i / C;
    int c   = i - row * C;
    float x = logits[i];
    float e = __expf(-x);
    float inv = frcp_approx(1.0f + e);
    float p = inv;          // sigmoid
    float q = e * inv;      // 1 - sigmoid, no cancellation
    float lp = __logf(p + 1e-8f);
    float lq = __logf(q + 1e-8f);
    float F2 = -0.5f * q * q * lp + 1.5f * p * p * lq;  // 2*(pos-neg)
    g_F[(row >> 2) * (4 * CP) + c * 4 + (row & 3)] = F2;
}

// ---------------------------- prep: row boxes -------------------------------
__global__ void prep_rows(const float* __restrict__ boxes, int BQ) {
    int r = blockIdx.x * blockDim.x + threadIdx.x;
    if (r >= BQ) return;
    float4 b = reinterpret_cast<const float4*>(boxes)[r];  // cx,cy,w,h
    g_rowA[r] = make_float4(5.f*b.x, 5.f*b.y, 5.f*b.z, 5.f*b.w);
    float x0 = b.x - 0.5f*b.z, y0 = b.y - 0.5f*b.w;
    float x1 = b.x + 0.5f*b.z, y1 = b.y + 0.5f*b.w;
    float w = x1 - x0, h = y1 - y0;
    g_rowB[r] = make_float4(-x0, -y0, x1, y1);
    g_rowE[r] = make_float4(w, h, w * h, 0.f);
}

// ---------------------------- prep: tgt boxes -------------------------------
__global__ void prep_tgts(const float* __restrict__ boxes,
                          const int* __restrict__ ids, int T) {
    int t = blockIdx.x * blockDim.x + threadIdx.x;
    if (t >= T) return;
    float4 b = reinterpret_cast<const float4*>(boxes)[t];
    g_tgtA[t] = make_float4(-5.f*b.x, -5.f*b.y, -5.f*b.z, -5.f*b.w);
    float x0 = b.x - 0.5f*b.z, y0 = b.y - 0.5f*b.w;
    float x1 = b.x + 0.5f*b.z, y1 = b.y + 0.5f*b.w;
    float w = x1 - x0, h = y1 - y0;
    g_tgtB[t] = make_float4(-x0, -y0, x1, y1);
    // class byte offset within a quad block: cls * 16
    g_tgtE[t] = make_float4(w, h, w * h, __int_as_float((ids[t] - 1) * 16));
}

// ---------------------------- main kernel -----------------------------------
// Block 256 threads = 32 rows x 192 targets (4800 = 25*192, 14400 = 450*32).
//   rr = tid>>6 -> rows row0 + rr*8 (two quads); tt = tid&63 -> 3 targets
#define ROW_TILE 32
#define TGT_TILE 192
#define RPT      8

__global__ void __launch_bounds__(256, 3)
cost_kernel(float* __restrict__ out, int T) {
    const int tid  = threadIdx.x;
    const int tt   = tid & 63;
    const int rr   = tid >> 6;
    const int row0 = blockIdx.y * ROW_TILE + rr * RPT;   // multiple of 8
    const int base = blockIdx.x * TGT_TILE + tt;

    // ---- 3 targets in registers (coalesced loads) ----
    unsigned long long taL[3], taH[3];   // packed (-5cx,-5cy) / (-5w,-5h)
    float4 tb[3], tE[3];
    const char* q[3];                    // gather base for quad0: cls*16 in
    {
        const char* fbase = reinterpret_cast<const char*>(g_F)
                          + (size_t)(row0 >> 2) * (4 * CP * 4);
        #pragma unroll
        for (int k = 0; k < 3; ++k) {
            const int j = base + (k << 6);
            ulonglong2 a = *reinterpret_cast<const ulonglong2*>(&g_tgtA[j]);
            taL[k] = a.x;  taH[k] = a.y;
            tb[k]  = g_tgtB[j];
            tE[k]  = g_tgtE[j];
            q[k]   = fbase + __float_as_int(tE[k].w);
        }
    }

    float* dst0 = out + (size_t)row0 * T + base;

    #pragma unroll
    for (int qp = 0; qp < 2; ++qp) {
        // 3 vector gathers: f2 for 4 rows x 3 classes (12 elements of work)
        float4 f4[3];
        #pragma unroll
        for (int k = 0; k < 3; ++k)
            f4[k] = __ldg(reinterpret_cast<const float4*>(
                        q[k] + qp * (4 * CP * 4)));

        #pragma unroll
        for (int r4 = 0; r4 < 4; ++r4) {
            const int r   = qp * 4 + r4;
            const int row = row0 + r;
            // warp-uniform row loads (broadcast, 1 wavefront each)
            const ulonglong2 rA2 =
                *reinterpret_cast<const ulonglong2*>(&g_rowA[row]);
            const float4 rB = g_rowB[row];
            const float4 rE = g_rowE[row];      // {wr, hr, area, -}
            float* dst = dst0 + (size_t)r * T;

            #pragma unroll
            for (int k = 0; k < 3; ++k) {
                const float f2 = reinterpret_cast<const float*>(&f4[k])[r4];

                // ---- 5*L1: packed diffs, abs folds into FADD ----
                unsigned long long dxy, dzw;
                ADD_F32X2(dxy, rA2.x, taL[k]);
                ADD_F32X2(dzw, rA2.y, taH[k]);
                float d0, d1, d2, d3;
                UNPACK2F(d0, d1, dxy);
                UNPACK2F(d2, d3, dzw);
                float bx = (fabsf(d0) + fabsf(d1)) + (fabsf(d2) + fabsf(d3));

                // ---- intersection corners (negated data) ----
                float mltx = fminf(rB.x, tb[k].x);   // = -max(x0a,x0b)
                float mlty = fminf(rB.y, tb[k].y);
                float rbx  = fminf(rB.z, tb[k].z);   // =  min(x1a,x1b)
                float rby  = fminf(rB.w, tb[k].w);
                float sw = rbx + mltx;               // signed inter width
                float sh = rby + mlty;
                float iw = fmaxf(sw, 0.0f);
                float ih = fmaxf(sh, 0.0f);
                float inter = iw * ih;

                // ---- enclosing via min+max=sum identity ----
                float encw = (rE.x + tE[k].x) - sw;
                float ench = (rE.y + tE[k].y) - sh;
                float enc  = encw * ench;

                float uni = (rE.z + tE[k].z) - inter;
                float dd  = enc - uni;
                float u = fmaxf(uni, 1e-6f);
                float e = fmaxf(enc, 1e-6f);
                float num = fmaf(dd, -u, inter * e); // giou = num/(u*e)
                float inv = frcp_approx(u * e);

                float res = fmaf(num * inv, -2.0f, f2 + bx);
                __stcs(dst + (k << 6), res);         // STG.CS, coalesced
            }
        }
    }
}

// ---------------------------------------------------------------------------
extern "C" void kernel_launch(void* const* d_in, const int* in_sizes, int n_in,
                              void* d_out, int out_size) {
    const float* pred_logits = (const float*)d_in[0];
    const float* pred_boxes  = (const float*)d_in[1];
    const int*   tgt_ids     = (const int*)d_in[2];
    const float* tgt_boxes   = (const float*)d_in[3];
    float* out = (float*)d_out;

    const int BQ = in_sizes[1] / 4;          // 14400
    const int C  = in_sizes[0] / BQ;         // 91
    const int T  = in_sizes[2];              // 4800

    prep_focal<<<(BQ * C + 255) / 256, 256>>>(pred_logits, BQ, C);
    prep_rows <<<(BQ + 255) / 256, 256>>>(pred_boxes, BQ);
    prep_tgts <<<(T + 255) / 256, 256>>>(tgt_boxes, tgt_ids, T);

    // exact tiling: 4800 = 25*192, 14400 = 450*32
    dim3 grid(T / TGT_TILE, BQ / ROW_TILE);
    cost_kernel<<<grid, 256>>>(out, T);
}